// round 3
// baseline (speedup 1.0000x reference)
#include <cuda_runtime.h>
#include <math.h>
#include <math_constants.h>

// Problem constants
#define BB 2
#define NN 2048
#define DIMX 768
#define HH 8
#define DKK 64
#define FF 192
#define NBASIS 32
#define LREL 4095            // 2*N - 1
#define QKVW 512             // H * DK

// ---------------- scratch (device globals; no allocation allowed) ----------
__device__ float g_pos[(size_t)LREL * FF];            // 3.1 MB
__device__ float g_relk[(size_t)LREL * QKVW];         // 8.4 MB  [idx][h*64+d]
__device__ float g_q[(size_t)BB * NN * QKVW];         // 8.4 MB  [b][n][h*64+d]
__device__ float g_k[(size_t)BB * NN * QKVW];
__device__ float g_v[(size_t)BB * NN * QKVW];
__device__ float g_o[(size_t)BB * NN * QKVW];
__device__ float g_S[(size_t)BB * HH * NN * NN];      // 268 MB

// ---------------- K1: positional embedding --------------------------------
__global__ void pos_embed_kernel() {
    int row = blockIdx.x;            // 0..4094
    int i = threadIdx.x;             // 0..31  (one basis per lane)
    float dist = (float)(row - (NN - 1));
    float ad = fabsf(dist);

    // exponential: half_life = 2^(3 + 8i/31), f = 2^(-ad/half_life)
    float half_life = exp2f(3.0f + 8.0f * (float)i / 31.0f);
    float f_exp = exp2f(-ad / half_life);

    // central mask: width = 2^(i+1) - 1
    float width = exp2f((float)(i + 1)) - 1.0f;
    float f_cm = (width > ad) ? 1.0f : 0.0f;

    // gamma pdf: stddev=32, mean=64*(i+1)
    float mean = 64.0f * (float)(i + 1);
    float conc = (mean / 32.0f) * (mean / 32.0f);
    float rate = mean / 1024.0f;
    float log_unnorm = (conc - 1.0f) * logf(ad) - rate * ad;   // ad=0 -> -inf, exp->0
    float log_norm = lgammaf(conc) - conc * logf(rate);
    float prob = expf(log_unnorm - log_norm) + 1e-8f;
    float pmax = prob;
    #pragma unroll
    for (int o = 16; o; o >>= 1) pmax = fmaxf(pmax, __shfl_xor_sync(0xFFFFFFFFu, pmax, o));
    float f_g = prob / pmax;

    float sgn = (dist > 0.0f) ? 1.0f : ((dist < 0.0f) ? -1.0f : 0.0f);

    float* out = g_pos + (size_t)row * FF;
    out[i]            = f_exp;
    out[32 + i]       = f_cm;
    out[64 + i]       = f_g;
    out[96 + i]       = sgn * f_exp;
    out[128 + i]      = sgn * f_cm;
    out[160 + i]      = sgn * f_g;
}

// ---------------- K2: generic fp32 GEMM, 64x64 tile, Kt=16 ------------------
// C[M,Nc] = A[M,K] @ B[K,Nc] (+ bias)
__global__ void gemm_kernel(const float* __restrict__ A, const float* __restrict__ B,
                            const float* __restrict__ bias, float* __restrict__ C,
                            int M, int K, int Nc) {
    __shared__ float As[16][65];   // [kk][mm]
    __shared__ float Bs[16][65];   // [kk][nn]
    int tid = threadIdx.x;
    int tx = tid & 15, ty = tid >> 4;
    int m0 = blockIdx.y * 64, n0 = blockIdx.x * 64;
    float acc[4][4] = {};

    for (int k0 = 0; k0 < K; k0 += 16) {
        for (int t = tid; t < 64 * 16; t += 256) {
            int mm = t >> 4, kk = t & 15;
            int m = m0 + mm, k = k0 + kk;
            As[kk][mm] = (m < M && k < K) ? A[(size_t)m * K + k] : 0.0f;
        }
        for (int t = tid; t < 16 * 64; t += 256) {
            int kk = t >> 6, nn = t & 63;
            int k = k0 + kk, n = n0 + nn;
            Bs[kk][nn] = (k < K && n < Nc) ? B[(size_t)k * Nc + n] : 0.0f;
        }
        __syncthreads();
        #pragma unroll
        for (int kk = 0; kk < 16; kk++) {
            float a[4], b[4];
            #pragma unroll
            for (int i = 0; i < 4; i++) a[i] = As[kk][ty * 4 + i];
            #pragma unroll
            for (int j = 0; j < 4; j++) b[j] = Bs[kk][tx * 4 + j];
            #pragma unroll
            for (int i = 0; i < 4; i++)
                #pragma unroll
                for (int j = 0; j < 4; j++) acc[i][j] += a[i] * b[j];
        }
        __syncthreads();
    }
    #pragma unroll
    for (int i = 0; i < 4; i++) {
        int m = m0 + ty * 4 + i;
        if (m >= M) continue;
        #pragma unroll
        for (int j = 0; j < 4; j++) {
            int n = n0 + tx * 4 + j;
            if (n < Nc) C[(size_t)m * Nc + n] = acc[i][j] + (bias ? bias[n] : 0.0f);
        }
    }
}

// ---------------- K3: logits (content + gathered rel) -----------------------
// S[b,h,i,j] = (0.125*q_i + rcb_h) . k_j  +  (0.125*q_i + rpb_h) . relk[j-i+N-1]
// tile: 64 i-rows x 32 j-cols; rel slice = 95 consecutive relk rows
__global__ void logits_kernel(const float* __restrict__ rcb, const float* __restrict__ rpb) {
    __shared__ float Qs[64][65];   // [d][li]
    __shared__ float Ks[64][97];   // [d][lj]  (phase1: 32 used) / [d][rr] (phase2: 95 used)
    int bh = blockIdx.z;
    int b = bh >> 3, h = bh & 7;
    int i0 = blockIdx.y * 64, j0 = blockIdx.x * 32;
    int tid = threadIdx.x;
    int tx = tid & 15, ty = tid >> 4;   // tx: 2 cols each, ty: 4 rows each

    const float* qb = g_q + (size_t)b * NN * QKVW + h * 64;
    const float* kb = g_k + (size_t)b * NN * QKVW + h * 64;

    float acc[4][2] = {};

    // ---- phase 1: content ----
    for (int t = tid; t < 64 * 64; t += 256) {
        int li = t >> 6, d = t & 63;
        Qs[d][li] = qb[(size_t)(i0 + li) * QKVW + d] * 0.125f + rcb[h * 64 + d];
    }
    for (int t = tid; t < 32 * 64; t += 256) {
        int lj = t >> 6, d = t & 63;
        Ks[d][lj] = kb[(size_t)(j0 + lj) * QKVW + d];
    }
    __syncthreads();
    #pragma unroll 4
    for (int d = 0; d < 64; d++) {
        float a[4], bv[2];
        #pragma unroll
        for (int i = 0; i < 4; i++) a[i] = Qs[d][ty * 4 + i];
        #pragma unroll
        for (int j = 0; j < 2; j++) bv[j] = Ks[d][tx * 2 + j];
        #pragma unroll
        for (int i = 0; i < 4; i++)
            #pragma unroll
            for (int j = 0; j < 2; j++) acc[i][j] += a[i] * bv[j];
    }
    __syncthreads();

    // ---- phase 2: relative (gathered Toeplitz band) ----
    int base = j0 - i0 + (NN - 1) - 63;   // relk row for (li=63, lj=0)
    for (int t = tid; t < 64 * 64; t += 256) {
        int li = t >> 6, d = t & 63;
        Qs[d][li] = qb[(size_t)(i0 + li) * QKVW + d] * 0.125f + rpb[h * 64 + d];
    }
    for (int t = tid; t < 95 * 64; t += 256) {
        int rr = t >> 6, d = t & 63;
        Ks[d][rr] = g_relk[(size_t)(base + rr) * QKVW + h * 64 + d];
    }
    __syncthreads();
    #pragma unroll 4
    for (int d = 0; d < 64; d++) {
        float a[4];
        #pragma unroll
        for (int i = 0; i < 4; i++) a[i] = Qs[d][ty * 4 + i];
        #pragma unroll
        for (int i = 0; i < 4; i++) {
            int li = ty * 4 + i;
            #pragma unroll
            for (int j = 0; j < 2; j++) {
                int lj = tx * 2 + j;
                acc[i][j] += a[i] * Ks[d][lj - li + 63];
            }
        }
    }

    size_t Sbase = ((size_t)bh * NN + i0) * NN + j0;
    #pragma unroll
    for (int i = 0; i < 4; i++)
        #pragma unroll
        for (int j = 0; j < 2; j++)
            g_S[Sbase + (size_t)(ty * 4 + i) * NN + tx * 2 + j] = acc[i][j];
}

// ---------------- K4: row softmax over 2048 --------------------------------
__global__ void softmax_kernel() {
    size_t row = blockIdx.x;
    float* Sr = g_S + row * NN;
    int tid = threadIdx.x;
    __shared__ float red[8];
    __shared__ float bcast;

    float vals[8];
    float m = -CUDART_INF_F;
    #pragma unroll
    for (int t = 0; t < 8; t++) {
        vals[t] = Sr[tid + t * 256];
        m = fmaxf(m, vals[t]);
    }
    #pragma unroll
    for (int o = 16; o; o >>= 1) m = fmaxf(m, __shfl_xor_sync(0xFFFFFFFFu, m, o));
    if ((tid & 31) == 0) red[tid >> 5] = m;
    __syncthreads();
    if (tid == 0) {
        float mm = red[0];
        #pragma unroll
        for (int w = 1; w < 8; w++) mm = fmaxf(mm, red[w]);
        bcast = mm;
    }
    __syncthreads();
    m = bcast;

    float s = 0.0f;
    #pragma unroll
    for (int t = 0; t < 8; t++) {
        vals[t] = expf(vals[t] - m);
        s += vals[t];
    }
    #pragma unroll
    for (int o = 16; o; o >>= 1) s += __shfl_xor_sync(0xFFFFFFFFu, s, o);
    __syncthreads();                  // protect red reuse
    if ((tid & 31) == 0) red[tid >> 5] = s;
    __syncthreads();
    if (tid == 0) {
        float ss = 0.0f;
        #pragma unroll
        for (int w = 0; w < 8; w++) ss += red[w];
        bcast = ss;
    }
    __syncthreads();
    float inv = 1.0f / bcast;
    #pragma unroll
    for (int t = 0; t < 8; t++) Sr[tid + t * 256] = vals[t] * inv;
}

// ---------------- K5: O = P @ V  (per b,h: [2048x2048]@[2048x64]) ----------
__global__ void pv_kernel() {
    __shared__ float Ps[32][65];   // [kk][mm]
    __shared__ float Vs[32][65];   // [kk][nn]
    int bh = blockIdx.y;
    int b = bh >> 3, h = bh & 7;
    int i0 = blockIdx.x * 64;
    int tid = threadIdx.x;
    int tx = tid & 15, ty = tid >> 4;

    const float* vb = g_v + (size_t)b * NN * QKVW + h * 64;
    size_t Sbase = ((size_t)bh * NN + i0) * NN;
    float acc[4][4] = {};

    for (int k0 = 0; k0 < NN; k0 += 32) {
        for (int t = tid; t < 64 * 32; t += 256) {
            int mm = t >> 5, kk = t & 31;
            Ps[kk][mm] = g_S[Sbase + (size_t)mm * NN + k0 + kk];
        }
        for (int t = tid; t < 32 * 64; t += 256) {
            int kk = t >> 6, nn = t & 63;
            Vs[kk][nn] = vb[(size_t)(k0 + kk) * QKVW + nn];
        }
        __syncthreads();
        #pragma unroll
        for (int kk = 0; kk < 32; kk++) {
            float a[4], bv[4];
            #pragma unroll
            for (int i = 0; i < 4; i++) a[i] = Ps[kk][ty * 4 + i];
            #pragma unroll
            for (int j = 0; j < 4; j++) bv[j] = Vs[kk][tx * 4 + j];
            #pragma unroll
            for (int i = 0; i < 4; i++)
                #pragma unroll
                for (int j = 0; j < 4; j++) acc[i][j] += a[i] * bv[j];
        }
        __syncthreads();
    }
    #pragma unroll
    for (int i = 0; i < 4; i++)
        #pragma unroll
        for (int j = 0; j < 4; j++)
            g_o[(size_t)(b * NN + i0 + ty * 4 + i) * QKVW + h * 64 + tx * 4 + j] = acc[i][j];
}

// ---------------- launch ----------------------------------------------------
static float* sym_addr(const void* sym) {
    void* p = nullptr;
    cudaGetSymbolAddress(&p, sym);
    return (float*)p;
}

extern "C" void kernel_launch(void* const* d_in, const int* in_sizes, int n_in,
                              void* d_out, int out_size) {
    const float* x    = (const float*)d_in[0];   // [2,2048,768]
    const float* Wq   = (const float*)d_in[1];   // [768,512]
    const float* Wk   = (const float*)d_in[2];
    const float* Wv   = (const float*)d_in[3];
    const float* Wrel = (const float*)d_in[4];   // [192,512]
    const float* Wout = (const float*)d_in[5];   // [512,768]
    const float* bout = (const float*)d_in[6];   // [768]
    const float* rcb  = (const float*)d_in[7];   // [1,8,1,64] -> 512
    const float* rpb  = (const float*)d_in[8];
    float* out = (float*)d_out;

    float* p_pos  = sym_addr(g_pos);
    float* p_relk = sym_addr(g_relk);
    float* p_q    = sym_addr(g_q);
    float* p_k    = sym_addr(g_k);
    float* p_v    = sym_addr(g_v);
    float* p_o    = sym_addr(g_o);

    // 1. positional embedding
    pos_embed_kernel<<<LREL, 32>>>();

    // 2. rel_k = pos @ Wrel : [4095,192]@[192,512]
    gemm_kernel<<<dim3(QKVW / 64, (LREL + 63) / 64), 256>>>(p_pos, Wrel, nullptr, p_relk,
                                                            LREL, FF, QKVW);

    // 3. q,k,v projections: [4096,768]@[768,512]
    gemm_kernel<<<dim3(QKVW / 64, (BB * NN) / 64), 256>>>(x, Wq, nullptr, p_q,
                                                          BB * NN, DIMX, QKVW);
    gemm_kernel<<<dim3(QKVW / 64, (BB * NN) / 64), 256>>>(x, Wk, nullptr, p_k,
                                                          BB * NN, DIMX, QKVW);
    gemm_kernel<<<dim3(QKVW / 64, (BB * NN) / 64), 256>>>(x, Wv, nullptr, p_v,
                                                          BB * NN, DIMX, QKVW);

    // 4. logits (content + gathered rel)
    logits_kernel<<<dim3(NN / 32, NN / 64, BB * HH), 256>>>(rcb, rpb);

    // 5. softmax over rows
    softmax_kernel<<<BB * HH * NN, 256>>>();

    // 6. O = P @ V
    pv_kernel<<<dim3(NN / 64, BB * HH), 256>>>();

    // 7. out = O @ Wout + b_out : [4096,512]@[512,768]
    gemm_kernel<<<dim3(DIMX / 64, (BB * NN) / 64), 256>>>(p_o, Wout, bout, out,
                                                          BB * NN, QKVW, DIMX);
}

// round 5
// speedup vs baseline: 1.3748x; 1.3748x over previous
#include <cuda_runtime.h>
#include <math.h>
#include <math_constants.h>
#include <stdint.h>

// Problem constants
#define BB 2
#define NN 2048
#define DIMX 768
#define HH 8
#define FF 192
#define LREL 4095            // 2*N - 1
#define QKVW 512             // H * DK

// ---------------- scratch (device globals; no allocation allowed) ----------
__device__ __align__(256) float g_pos[(size_t)LREL * FF];      // 3.1 MB
__device__ __align__(256) float g_relk[(size_t)LREL * QKVW];   // 8.4 MB  [idx][h*64+d]
__device__ __align__(256) float g_q[(size_t)BB * NN * QKVW];   // 8.4 MB  [b][n][h*64+d]
__device__ __align__(256) float g_k[(size_t)BB * NN * QKVW];
__device__ __align__(256) float g_v[(size_t)BB * NN * QKVW];
__device__ __align__(256) float g_o[(size_t)BB * NN * QKVW];
__device__ __align__(256) float g_S[(size_t)BB * HH * NN * NN]; // 268 MB

// ---------------- tf32 mma helpers -----------------------------------------
__device__ __forceinline__ uint32_t f2tf(float x) {
    uint32_t r;
    asm("cvt.rna.tf32.f32 %0, %1;" : "=r"(r) : "f"(x));
    return r;
}
// two-term split: x ~= hi + lo, both representable in tf32
__device__ __forceinline__ void tfsplit(float x, uint32_t& hi, uint32_t& lo) {
    hi = f2tf(x);
    lo = f2tf(x - __uint_as_float(hi));
}

// D += A(m16k8,row) * B(k8n8,col)   fragments per PTX ISA m16n8k8 tf32
__device__ __forceinline__ void mma8(float* d, const uint32_t* a, const uint32_t* b) {
    asm volatile(
        "mma.sync.aligned.m16n8k8.row.col.f32.tf32.tf32.f32 "
        "{%0,%1,%2,%3},{%4,%5,%6,%7},{%8,%9},{%0,%1,%2,%3};\n"
        : "+f"(d[0]), "+f"(d[1]), "+f"(d[2]), "+f"(d[3])
        : "r"(a[0]), "r"(a[1]), "r"(a[2]), "r"(a[3]), "r"(b[0]), "r"(b[1]));
}
// tf32x3 accumulate: d += ahi*bhi + ahi*blo + alo*bhi
__device__ __forceinline__ void mma8x3(float* d, const uint32_t* ahi, const uint32_t* alo,
                                       const uint32_t* bhi, const uint32_t* blo) {
    mma8(d, ahi, blo);
    mma8(d, alo, bhi);
    mma8(d, ahi, bhi);
}

// ---------------- K1: positional embedding ----------------------------------
__global__ void pos_embed_kernel() {
    int row = blockIdx.x;            // 0..4094
    int i = threadIdx.x;             // 0..31
    float dist = (float)(row - (NN - 1));
    float ad = fabsf(dist);

    float half_life = exp2f(3.0f + 8.0f * (float)i / 31.0f);
    float f_exp = exp2f(-ad / half_life);

    float width = exp2f((float)(i + 1)) - 1.0f;
    float f_cm = (width > ad) ? 1.0f : 0.0f;

    float mean = 64.0f * (float)(i + 1);
    float conc = (mean / 32.0f) * (mean / 32.0f);
    float rate = mean / 1024.0f;
    float log_unnorm = (conc - 1.0f) * logf(ad) - rate * ad;
    float log_norm = lgammaf(conc) - conc * logf(rate);
    float prob = expf(log_unnorm - log_norm) + 1e-8f;
    float pmax = prob;
    #pragma unroll
    for (int o = 16; o; o >>= 1) pmax = fmaxf(pmax, __shfl_xor_sync(0xFFFFFFFFu, pmax, o));
    float f_g = prob / pmax;

    float sgn = (dist > 0.0f) ? 1.0f : ((dist < 0.0f) ? -1.0f : 0.0f);

    float* out = g_pos + (size_t)row * FF;
    out[i]       = f_exp;
    out[32 + i]  = f_cm;
    out[64 + i]  = f_g;
    out[96 + i]  = sgn * f_exp;
    out[128 + i] = sgn * f_cm;
    out[160 + i] = sgn * f_g;
}

// ---------------- K2: generic tf32x3 tensor-core GEMM -----------------------
// C[M,Nc] = A[M,K] @ B[K,Nc] (+bias), strided; pvmode batches over blockIdx.z (bh).
// Block tile 128x64, 8 warps (4m x 2n), warp tile 32x32, k-step 32.
#define AS_STRIDE 136   // m-stride of As[k][m]
#define BS_STRIDE 72    // n-stride of Bs[k][n]
__global__ void gemm_tf32(const float* __restrict__ A, const float* __restrict__ B,
                          const float* __restrict__ bias, float* __restrict__ C,
                          int M, int K, int Nc, int lda, int ldb, int ldc, int pvmode) {
    __shared__ float As[32 * AS_STRIDE];
    __shared__ float Bs[32 * BS_STRIDE];

    if (pvmode) {
        int z = blockIdx.z;
        A += (size_t)z * NN * NN;
        size_t off = (size_t)(z >> 3) * NN * QKVW + (size_t)(z & 7) * 64;
        B += off;
        C += off;
    }

    int tid = threadIdx.x;
    int warp = tid >> 5, lane = tid & 31;
    int g = lane >> 2, tig = lane & 3;
    int mw = (warp >> 1) * 32, nw = (warp & 1) * 32;
    int m0 = blockIdx.y * 128, n0 = blockIdx.x * 64;

    float acc[2][4][4] = {};

    int arow = tid >> 3;            // 0..31
    int ak = (tid & 7) * 4;         // 0..28
    int bk = tid >> 3;              // 0..31
    int bn = (tid & 7) * 8;         // 0..56

    for (int k0 = 0; k0 < K; k0 += 32) {
        #pragma unroll
        for (int r = 0; r < 4; r++) {
            int ml = arow + 32 * r;
            int m = m0 + ml;
            float4 av = make_float4(0.f, 0.f, 0.f, 0.f);
            if (m < M) av = *(const float4*)(A + (size_t)m * lda + k0 + ak);
            As[(ak + 0) * AS_STRIDE + ml] = av.x;
            As[(ak + 1) * AS_STRIDE + ml] = av.y;
            As[(ak + 2) * AS_STRIDE + ml] = av.z;
            As[(ak + 3) * AS_STRIDE + ml] = av.w;
        }
        {
            const float* bp = B + (size_t)(k0 + bk) * ldb + n0 + bn;
            float4 b0 = *(const float4*)bp;
            float4 b1 = *(const float4*)(bp + 4);
            Bs[bk * BS_STRIDE + bn + 0] = b0.x;
            Bs[bk * BS_STRIDE + bn + 1] = b0.y;
            Bs[bk * BS_STRIDE + bn + 2] = b0.z;
            Bs[bk * BS_STRIDE + bn + 3] = b0.w;
            Bs[bk * BS_STRIDE + bn + 4] = b1.x;
            Bs[bk * BS_STRIDE + bn + 5] = b1.y;
            Bs[bk * BS_STRIDE + bn + 6] = b1.z;
            Bs[bk * BS_STRIDE + bn + 7] = b1.w;
        }
        __syncthreads();
        #pragma unroll
        for (int kk = 0; kk < 32; kk += 8) {
            uint32_t ah[2][4], al[2][4];
            #pragma unroll
            for (int f = 0; f < 2; f++) {
                int mb = mw + 16 * f;
                tfsplit(As[(kk + tig) * AS_STRIDE + mb + g],         ah[f][0], al[f][0]);
                tfsplit(As[(kk + tig) * AS_STRIDE + mb + g + 8],     ah[f][1], al[f][1]);
                tfsplit(As[(kk + tig + 4) * AS_STRIDE + mb + g],     ah[f][2], al[f][2]);
                tfsplit(As[(kk + tig + 4) * AS_STRIDE + mb + g + 8], ah[f][3], al[f][3]);
            }
            #pragma unroll
            for (int j = 0; j < 4; j++) {
                uint32_t bh2[2], bl2[2];
                tfsplit(Bs[(kk + tig) * BS_STRIDE + nw + 8 * j + g],     bh2[0], bl2[0]);
                tfsplit(Bs[(kk + tig + 4) * BS_STRIDE + nw + 8 * j + g], bh2[1], bl2[1]);
                mma8x3(acc[0][j], ah[0], al[0], bh2, bl2);
                mma8x3(acc[1][j], ah[1], al[1], bh2, bl2);
            }
        }
        __syncthreads();
    }

    #pragma unroll
    for (int f = 0; f < 2; f++) {
        #pragma unroll
        for (int j = 0; j < 4; j++) {
            int n = n0 + nw + 8 * j + 2 * tig;
            float b0v = bias ? bias[n] : 0.0f;
            float b1v = bias ? bias[n + 1] : 0.0f;
            int m = m0 + mw + 16 * f + g;
            if (m < M)
                *(float2*)(C + (size_t)m * ldc + n) =
                    make_float2(acc[f][j][0] + b0v, acc[f][j][1] + b1v);
            if (m + 8 < M)
                *(float2*)(C + (size_t)(m + 8) * ldc + n) =
                    make_float2(acc[f][j][2] + b0v, acc[f][j][3] + b1v);
        }
    }
}

// ---------------- K3: logits via tf32x3 mma + Toeplitz band gather ----------
// S[b,h,i,j] = (0.125*q_i + rcb_h).k_j + (0.125*q_i + rpb_h).relk[j-i+N-1]
#define QS_STRIDE 72
#define RS_STRIDE 136
__global__ void logits_tf32(const float* __restrict__ rcb, const float* __restrict__ rpb) {
    extern __shared__ float sm[];
    float* Qs = sm;                         // [64][QS_STRIDE]: Qs[d*72 + li]
    float* Rs = sm + 64 * QS_STRIDE;        // [64][RS_STRIDE]: Rs[d*136 + u]
    float* Gs = Rs;                         // reuse: Gs[li*136 + u]

    int bh = blockIdx.z;
    int b = bh >> 3, h = bh & 7;
    int i0 = blockIdx.y * 64, j0 = blockIdx.x * 64;
    int tid = threadIdx.x;
    int warp = tid >> 5, lane = tid & 31;
    int g = lane >> 2, tig = lane & 3;
    int mwl = (warp >> 1) * 16;       // warp row base (4 warps over 64 rows)
    int nwl = (warp & 1) * 32;        // content col base (2 warps over 64 cols)

    const float* qb = g_q + (size_t)b * NN * QKVW + (size_t)h * 64;
    const float* kb = g_k + (size_t)b * NN * QKVW + (size_t)h * 64;

    int d4 = (tid & 15) * 4;
    int lrow = tid >> 4;              // 0..15
    float4 rc = *(const float4*)(rcb + h * 64 + d4);
    float4 rp = *(const float4*)(rpb + h * 64 + d4);

    // ---- phase A loads ----
    #pragma unroll
    for (int r = 0; r < 4; r++) {
        int li = lrow + 16 * r;
        float4 qv = *(const float4*)(qb + (size_t)(i0 + li) * QKVW + d4);
        Qs[(d4 + 0) * QS_STRIDE + li] = qv.x * 0.125f + rc.x;
        Qs[(d4 + 1) * QS_STRIDE + li] = qv.y * 0.125f + rc.y;
        Qs[(d4 + 2) * QS_STRIDE + li] = qv.z * 0.125f + rc.z;
        Qs[(d4 + 3) * QS_STRIDE + li] = qv.w * 0.125f + rc.w;
        float4 kv = *(const float4*)(kb + (size_t)(j0 + li) * QKVW + d4);
        Rs[(d4 + 0) * RS_STRIDE + li] = kv.x;
        Rs[(d4 + 1) * RS_STRIDE + li] = kv.y;
        Rs[(d4 + 2) * RS_STRIDE + li] = kv.z;
        Rs[(d4 + 3) * RS_STRIDE + li] = kv.w;
    }
    __syncthreads();

    float cacc[4][4] = {};
    #pragma unroll
    for (int kk = 0; kk < 64; kk += 8) {
        uint32_t ah[4], al[4];
        tfsplit(Qs[(kk + tig) * QS_STRIDE + mwl + g],         ah[0], al[0]);
        tfsplit(Qs[(kk + tig) * QS_STRIDE + mwl + g + 8],     ah[1], al[1]);
        tfsplit(Qs[(kk + tig + 4) * QS_STRIDE + mwl + g],     ah[2], al[2]);
        tfsplit(Qs[(kk + tig + 4) * QS_STRIDE + mwl + g + 8], ah[3], al[3]);
        #pragma unroll
        for (int j = 0; j < 4; j++) {
            uint32_t bh2[2], bl2[2];
            tfsplit(Rs[(kk + tig) * RS_STRIDE + nwl + 8 * j + g],     bh2[0], bl2[0]);
            tfsplit(Rs[(kk + tig + 4) * RS_STRIDE + nwl + 8 * j + g], bh2[1], bl2[1]);
            mma8x3(cacc[j], ah, al, bh2, bl2);
        }
    }
    __syncthreads();

    // ---- phase B: G[64x128] = Qp @ relband^T ----
    int base = j0 - i0 + (NN - 1) - 63;   // band [base, base+128)
    #pragma unroll
    for (int r = 0; r < 4; r++) {
        int li = lrow + 16 * r;
        float4 qv = *(const float4*)(qb + (size_t)(i0 + li) * QKVW + d4);
        Qs[(d4 + 0) * QS_STRIDE + li] = qv.x * 0.125f + rp.x;
        Qs[(d4 + 1) * QS_STRIDE + li] = qv.y * 0.125f + rp.y;
        Qs[(d4 + 2) * QS_STRIDE + li] = qv.z * 0.125f + rp.z;
        Qs[(d4 + 3) * QS_STRIDE + li] = qv.w * 0.125f + rp.w;
    }
    #pragma unroll
    for (int r = 0; r < 8; r++) {
        int u = lrow + 16 * r;
        float4 rv = *(const float4*)(g_relk + (size_t)(base + u) * QKVW + h * 64 + d4);
        Rs[(d4 + 0) * RS_STRIDE + u] = rv.x;
        Rs[(d4 + 1) * RS_STRIDE + u] = rv.y;
        Rs[(d4 + 2) * RS_STRIDE + u] = rv.z;
        Rs[(d4 + 3) * RS_STRIDE + u] = rv.w;
    }
    __syncthreads();

    float gacc[8][4] = {};
    int nwg = (warp & 1) * 64;
    #pragma unroll
    for (int kk = 0; kk < 64; kk += 8) {
        uint32_t ah[4], al[4];
        tfsplit(Qs[(kk + tig) * QS_STRIDE + mwl + g],         ah[0], al[0]);
        tfsplit(Qs[(kk + tig) * QS_STRIDE + mwl + g + 8],     ah[1], al[1]);
        tfsplit(Qs[(kk + tig + 4) * QS_STRIDE + mwl + g],     ah[2], al[2]);
        tfsplit(Qs[(kk + tig + 4) * QS_STRIDE + mwl + g + 8], ah[3], al[3]);
        #pragma unroll
        for (int j = 0; j < 8; j++) {
            uint32_t bh2[2], bl2[2];
            tfsplit(Rs[(kk + tig) * RS_STRIDE + nwg + 8 * j + g],     bh2[0], bl2[0]);
            tfsplit(Rs[(kk + tig + 4) * RS_STRIDE + nwg + 8 * j + g], bh2[1], bl2[1]);
            mma8x3(gacc[j], ah, al, bh2, bl2);
        }
    }
    __syncthreads();   // all warps done reading Rs

    #pragma unroll
    for (int j = 0; j < 8; j++) {
        int u = nwg + 8 * j + 2 * tig;
        int li = mwl + g;
        *(float2*)&Gs[li * RS_STRIDE + u] = make_float2(gacc[j][0], gacc[j][1]);
        *(float2*)&Gs[(li + 8) * RS_STRIDE + u] = make_float2(gacc[j][2], gacc[j][3]);
    }
    __syncthreads();

    float* Sout = g_S + ((size_t)bh * NN + i0) * NN + j0;
    #pragma unroll
    for (int j = 0; j < 4; j++) {
        int lj = nwl + 8 * j + 2 * tig;
        int li = mwl + g;
        float o0 = cacc[j][0] + Gs[li * RS_STRIDE + (lj - li + 63)];
        float o1 = cacc[j][1] + Gs[li * RS_STRIDE + (lj + 1 - li + 63)];
        *(float2*)(Sout + (size_t)li * NN + lj) = make_float2(o0, o1);
        int li2 = li + 8;
        float o2 = cacc[j][2] + Gs[li2 * RS_STRIDE + (lj - li2 + 63)];
        float o3 = cacc[j][3] + Gs[li2 * RS_STRIDE + (lj + 1 - li2 + 63)];
        *(float2*)(Sout + (size_t)li2 * NN + lj) = make_float2(o2, o3);
    }
}

// ---------------- K4: row softmax over 2048 (vectorized) --------------------
__global__ void softmax_kernel() {
    size_t row = blockIdx.x;
    float4* Sr = (float4*)(g_S + row * NN);
    int tid = threadIdx.x;
    __shared__ float red[8];
    __shared__ float bcast;

    float4 v0 = Sr[tid];
    float4 v1 = Sr[tid + 256];
    float m = fmaxf(fmaxf(fmaxf(v0.x, v0.y), fmaxf(v0.z, v0.w)),
                    fmaxf(fmaxf(v1.x, v1.y), fmaxf(v1.z, v1.w)));
    #pragma unroll
    for (int o = 16; o; o >>= 1) m = fmaxf(m, __shfl_xor_sync(0xFFFFFFFFu, m, o));
    if ((tid & 31) == 0) red[tid >> 5] = m;
    __syncthreads();
    if (tid == 0) {
        float mm = red[0];
        #pragma unroll
        for (int w = 1; w < 8; w++) mm = fmaxf(mm, red[w]);
        bcast = mm;
    }
    __syncthreads();
    m = bcast;

    v0.x = expf(v0.x - m); v0.y = expf(v0.y - m); v0.z = expf(v0.z - m); v0.w = expf(v0.w - m);
    v1.x = expf(v1.x - m); v1.y = expf(v1.y - m); v1.z = expf(v1.z - m); v1.w = expf(v1.w - m);
    float s = v0.x + v0.y + v0.z + v0.w + v1.x + v1.y + v1.z + v1.w;
    #pragma unroll
    for (int o = 16; o; o >>= 1) s += __shfl_xor_sync(0xFFFFFFFFu, s, o);
    __syncthreads();
    if ((tid & 31) == 0) red[tid >> 5] = s;
    __syncthreads();
    if (tid == 0) {
        float ss = 0.0f;
        #pragma unroll
        for (int w = 0; w < 8; w++) ss += red[w];
        bcast = ss;
    }
    __syncthreads();
    float inv = 1.0f / bcast;
    v0.x *= inv; v0.y *= inv; v0.z *= inv; v0.w *= inv;
    v1.x *= inv; v1.y *= inv; v1.z *= inv; v1.w *= inv;
    Sr[tid] = v0;
    Sr[tid + 256] = v1;
}

// ---------------- launch ----------------------------------------------------
static float* sym_addr(const void* sym) {
    void* p = nullptr;
    cudaGetSymbolAddress(&p, sym);
    return (float*)p;
}

extern "C" void kernel_launch(void* const* d_in, const int* in_sizes, int n_in,
                              void* d_out, int out_size) {
    const float* x    = (const float*)d_in[0];
    const float* Wq   = (const float*)d_in[1];
    const float* Wk   = (const float*)d_in[2];
    const float* Wv   = (const float*)d_in[3];
    const float* Wrel = (const float*)d_in[4];
    const float* Wout = (const float*)d_in[5];
    const float* bout = (const float*)d_in[6];
    const float* rcb  = (const float*)d_in[7];
    const float* rpb  = (const float*)d_in[8];
    float* out = (float*)d_out;

    float* p_pos  = sym_addr(g_pos);
    float* p_relk = sym_addr(g_relk);
    float* p_q    = sym_addr(g_q);
    float* p_k    = sym_addr(g_k);
    float* p_v    = sym_addr(g_v);
    float* p_o    = sym_addr(g_o);
    float* p_S    = sym_addr(g_S);

    const int LOGITS_SMEM = (64 * QS_STRIDE + 64 * RS_STRIDE) * 4;  // 53248
    cudaFuncSetAttribute(logits_tf32, cudaFuncAttributeMaxDynamicSharedMemorySize,
                         LOGITS_SMEM);

    // 1. positional embedding
    pos_embed_kernel<<<LREL, 32>>>();

    // 2. rel_k = pos @ Wrel
    gemm_tf32<<<dim3(QKVW / 64, 32), 256>>>(p_pos, Wrel, nullptr, p_relk,
                                            LREL, FF, QKVW, FF, QKVW, QKVW, 0);

    // 3. q,k,v projections
    gemm_tf32<<<dim3(QKVW / 64, (BB * NN) / 128), 256>>>(x, Wq, nullptr, p_q,
                                                         BB * NN, DIMX, QKVW, DIMX, QKVW, QKVW, 0);
    gemm_tf32<<<dim3(QKVW / 64, (BB * NN) / 128), 256>>>(x, Wk, nullptr, p_k,
                                                         BB * NN, DIMX, QKVW, DIMX, QKVW, QKVW, 0);
    gemm_tf32<<<dim3(QKVW / 64, (BB * NN) / 128), 256>>>(x, Wv, nullptr, p_v,
                                                         BB * NN, DIMX, QKVW, DIMX, QKVW, QKVW, 0);

    // 4. logits (content + gathered rel)
    logits_tf32<<<dim3(NN / 64, NN / 64, BB * HH), 256, LOGITS_SMEM>>>(rcb, rpb);

    // 5. softmax
    softmax_kernel<<<BB * HH * NN, 256>>>();

    // 6. O = P @ V  (batched over bh)
    gemm_tf32<<<dim3(1, NN / 128, BB * HH), 256>>>(p_S, p_v, nullptr, p_o,
                                                   NN, NN, 64, NN, QKVW, QKVW, 1);

    // 7. out = O @ Wout + b_out
    gemm_tf32<<<dim3(DIMX / 64, (BB * NN) / 128), 256>>>(p_o, Wout, bout, out,
                                                         BB * NN, QKVW, DIMX, QKVW, DIMX, DIMX, 0);
}